// round 1
// baseline (speedup 1.0000x reference)
#include <cuda_runtime.h>
#include <cuda_bf16.h>
#include <math.h>

// Problem constants
#define Bv   4
#define Cv   256
#define Hv   64
#define Wv   64
#define HW   4096          // Hv*Wv
#define NPIX 16384         // Bv*HW
#define NEL  4194304       // Bv*Cv*HW
#define NHEAD 8
#define DHEAD 32

// Scratch: 9 tensors of NEL floats (~151 MB), device global (no allocation).
__device__ float g_scratch[9u * NEL];

// ---------------------------------------------------------------------------
// conv1x1 as GEMM: Y[o, n] = sum_c W[o,c] * X[c, n], per-batch layout
// X element (b, c, p) at X[((b*Cv + c) << 12) + p], n = b*HW + p.
// BM=64, BN=64, BK=16, 256 threads, 4x4 microtile per thread.
// ---------------------------------------------------------------------------
template<bool RELU, bool BIAS, bool RES>
__global__ void conv1x1_kernel(const float* __restrict__ X,
                               const float* __restrict__ Wm,
                               const float* __restrict__ bias,
                               const float* __restrict__ res,
                               float* __restrict__ Y)
{
    const int BM = 64, BN = 64, BK = 16;
    __shared__ float Ws[BK][BM + 1];
    __shared__ float Xs[BK][BN];

    const int tb_n = blockIdx.x * BN;      // global column start
    const int tb_m = blockIdx.y * BM;      // output-channel start
    const int b    = tb_n >> 12;           // batch (BN divides HW)
    const int p0   = tb_n & 4095;          // pixel offset within batch

    const float* Xbase = X + ((size_t)(b * Cv) << 12) + p0;

    const int t  = threadIdx.x;
    const int tx = t & 15;                 // column group
    const int ty = t >> 4;                 // row group

    float acc[4][4] = {};

    for (int k0 = 0; k0 < Cv; k0 += BK) {
        // Load W tile: 64 (m) x 16 (k), transposed into Ws[k][m]
        #pragma unroll
        for (int i = 0; i < 4; i++) {
            int e  = t * 4 + i;            // 0..1023
            int m  = e >> 4;
            int kk = e & 15;
            Ws[kk][m] = Wm[(tb_m + m) * Cv + k0 + kk];
        }
        // Load X tile: 16 (k) x 64 (n)
        #pragma unroll
        for (int i = 0; i < 4; i++) {
            int e  = t + i * 256;
            int kk = e >> 6;
            int nn = e & 63;
            Xs[kk][nn] = Xbase[((k0 + kk) << 12) + nn];
        }
        __syncthreads();

        #pragma unroll
        for (int kk = 0; kk < BK; kk++) {
            float a[4], bb[4];
            #pragma unroll
            for (int i = 0; i < 4; i++) a[i]  = Ws[kk][ty * 4 + i];
            #pragma unroll
            for (int j = 0; j < 4; j++) bb[j] = Xs[kk][tx * 4 + j];
            #pragma unroll
            for (int i = 0; i < 4; i++)
                #pragma unroll
                for (int j = 0; j < 4; j++)
                    acc[i][j] = fmaf(a[i], bb[j], acc[i][j]);
        }
        __syncthreads();
    }

    // Epilogue
    #pragma unroll
    for (int i = 0; i < 4; i++) {
        int m = tb_m + ty * 4 + i;
        float bv = BIAS ? bias[m] : 0.0f;
        size_t rowoff = ((size_t)(b * Cv + m) << 12) + p0;
        #pragma unroll
        for (int j = 0; j < 4; j++) {
            int nn = tx * 4 + j;
            float v = acc[i][j] + bv;
            if (RELU) v = fmaxf(v, 0.0f);
            if (RES)  v += res[rowoff + nn];
            Y[rowoff + nn] = v;
        }
    }
}

// ---------------------------------------------------------------------------
// Local 3x3 windowed attention, one thread per (b, head, pixel).
// Zero-padded out-of-bounds neighbors give logit = 0 (unfold semantics) and
// zero V contribution.
// ---------------------------------------------------------------------------
__global__ void local_attn_kernel(const float* __restrict__ Q,
                                  const float* __restrict__ K,
                                  const float* __restrict__ V,
                                  float* __restrict__ O)
{
    int n = blockIdx.x * blockDim.x + threadIdx.x;   // 0 .. 131071
    int p    = n & 4095;
    int x    = p & 63;
    int y    = p >> 6;
    int head = (n >> 12) & 7;
    int b    = n >> 15;

    size_t chbase = ((size_t)(b * Cv + head * DHEAD)) << 12;

    float q[DHEAD];
    #pragma unroll
    for (int d = 0; d < DHEAD; d++) q[d] = Q[chbase + ((size_t)d << 12) + p];

    const float scale = 0.17677669529663687f; // 1/sqrt(32)

    float logits[9];
    #pragma unroll
    for (int ki = 0; ki < 3; ki++) {
        #pragma unroll
        for (int kj = 0; kj < 3; kj++) {
            int yy = y + ki - 1, xx = x + kj - 1;
            float acc = 0.0f;
            if (yy >= 0 && yy < Hv && xx >= 0 && xx < Wv) {
                int pp = yy * Wv + xx;
                #pragma unroll
                for (int d = 0; d < DHEAD; d++)
                    acc = fmaf(q[d], K[chbase + ((size_t)d << 12) + pp], acc);
                acc *= scale;
            }
            logits[ki * 3 + kj] = acc;
        }
    }

    float m = logits[0];
    #pragma unroll
    for (int i = 1; i < 9; i++) m = fmaxf(m, logits[i]);
    float wgt[9]; float s = 0.0f;
    #pragma unroll
    for (int i = 0; i < 9; i++) { wgt[i] = __expf(logits[i] - m); s += wgt[i]; }
    float inv = 1.0f / s;
    #pragma unroll
    for (int i = 0; i < 9; i++) wgt[i] *= inv;

    #pragma unroll
    for (int d = 0; d < DHEAD; d++) {
        float acc = 0.0f;
        #pragma unroll
        for (int ki = 0; ki < 3; ki++) {
            #pragma unroll
            for (int kj = 0; kj < 3; kj++) {
                int yy = y + ki - 1, xx = x + kj - 1;
                if (yy >= 0 && yy < Hv && xx >= 0 && xx < Wv)
                    acc = fmaf(wgt[ki * 3 + kj],
                               V[chbase + ((size_t)d << 12) + yy * Wv + xx], acc);
            }
        }
        O[chbase + ((size_t)d << 12) + p] = acc;
    }
}

// ---------------------------------------------------------------------------
// LayerNorm over channel dim, one thread per pixel (coalesced across pixels).
// ---------------------------------------------------------------------------
__global__ void layernorm_kernel(const float* __restrict__ X,
                                 const float* __restrict__ g,
                                 const float* __restrict__ bt,
                                 float* __restrict__ Y)
{
    int n = blockIdx.x * blockDim.x + threadIdx.x;   // 0 .. 16383
    int b = n >> 12, p = n & 4095;
    const float* xp = X + (((size_t)b * Cv) << 12) + p;
    float s = 0.0f, s2 = 0.0f;
    for (int c = 0; c < Cv; c++) {
        float v = xp[(size_t)c << 12];
        s += v; s2 += v * v;
    }
    float mu   = s * (1.0f / Cv);
    float var  = s2 * (1.0f / Cv) - mu * mu;
    float rstd = rsqrtf(var + 1e-6f);
    float* yp = Y + (((size_t)b * Cv) << 12) + p;
    for (int c = 0; c < Cv; c++) {
        float v = xp[(size_t)c << 12];
        yp[(size_t)c << 12] = (v - mu) * rstd * g[c] + bt[c];
    }
}

// ---------------------------------------------------------------------------
// BatchNorm over (B,H,W) per channel, fused +residual. One block per channel.
// ---------------------------------------------------------------------------
__global__ void batchnorm_kernel(const float* __restrict__ X,
                                 const float* __restrict__ g,
                                 const float* __restrict__ bt,
                                 const float* __restrict__ res,
                                 float* __restrict__ Y)
{
    int c = blockIdx.x;
    __shared__ float ssum[256], ssum2[256];
    float s = 0.0f, s2 = 0.0f;
    for (int b = 0; b < Bv; b++) {
        const float* xp = X + (((size_t)(b * Cv + c)) << 12);
        for (int p = threadIdx.x; p < HW; p += 256) {
            float v = xp[p];
            s += v; s2 += v * v;
        }
    }
    ssum[threadIdx.x] = s; ssum2[threadIdx.x] = s2;
    __syncthreads();
    for (int off = 128; off > 0; off >>= 1) {
        if (threadIdx.x < off) {
            ssum[threadIdx.x]  += ssum[threadIdx.x + off];
            ssum2[threadIdx.x] += ssum2[threadIdx.x + off];
        }
        __syncthreads();
    }
    float mu   = ssum[0] * (1.0f / (Bv * HW));
    float var  = ssum2[0] * (1.0f / (Bv * HW)) - mu * mu;
    float rstd = rsqrtf(var + 1e-5f);
    float gg = g[c], bb = bt[c];
    for (int b = 0; b < Bv; b++) {
        size_t off = ((size_t)(b * Cv + c)) << 12;
        for (int p = threadIdx.x; p < HW; p += 256)
            Y[off + p] = (X[off + p] - mu) * rstd * gg + bb + res[off + p];
    }
}

// ---------------------------------------------------------------------------
// Host-side orchestration
// ---------------------------------------------------------------------------
static void run_mha(const float* xq, const float* xkv,
                    const float* wq, const float* wk, const float* wv,
                    const float* wfc, const float* g, const float* bt,
                    float* out, float* Qb, float* Kb, float* Vb, float* Ob)
{
    dim3 gg(NPIX / 64, Cv / 64), bb(256);
    conv1x1_kernel<false, false, false><<<gg, bb>>>(xq,  wq, nullptr, nullptr, Qb);
    conv1x1_kernel<false, false, false><<<gg, bb>>>(xkv, wk, nullptr, nullptr, Kb);
    conv1x1_kernel<false, false, false><<<gg, bb>>>(xkv, wv, nullptr, nullptr, Vb);
    local_attn_kernel<<<(Bv * NHEAD * HW) / 256, 256>>>(Qb, Kb, Vb, Ob);
    conv1x1_kernel<false, false, true ><<<gg, bb>>>(Ob, wfc, nullptr, xq, Qb);
    layernorm_kernel<<<NPIX / 256, 256>>>(Qb, g, bt, out);
}

static void run_ffn(const float* x,
                    const float* w1, const float* b1,
                    const float* w2, const float* b2,
                    const float* g, const float* bt,
                    float* out, float* Hh, float* Tmp)
{
    dim3 gg(NPIX / 64, Cv / 64), bb(256);
    conv1x1_kernel<true,  true, false><<<gg, bb>>>(x,  w1, b1, nullptr, Hh);
    conv1x1_kernel<false, true, false><<<gg, bb>>>(Hh, w2, b2, nullptr, Tmp);
    batchnorm_kernel<<<Cv, 256>>>(Tmp, g, bt, x, out);
}

extern "C" void kernel_launch(void* const* d_in, const int* in_sizes, int n_in,
                              void* d_out, int out_size)
{
    const float* input1 = (const float*)d_in[0];
    const float* input2 = (const float*)d_in[1];
    const float* slf_wq = (const float*)d_in[2];
    const float* slf_wk = (const float*)d_in[3];
    const float* slf_wv = (const float*)d_in[4];
    const float* slf_fc = (const float*)d_in[5];
    const float* slf_g  = (const float*)d_in[6];
    const float* slf_b  = (const float*)d_in[7];
    const float* crs_wq = (const float*)d_in[8];
    const float* crs_wk = (const float*)d_in[9];
    const float* crs_wv = (const float*)d_in[10];
    const float* crs_fc = (const float*)d_in[11];
    const float* crs_g  = (const float*)d_in[12];
    const float* crs_b  = (const float*)d_in[13];
    const float* ffn_w1 = (const float*)d_in[14];
    const float* ffn_b1 = (const float*)d_in[15];
    const float* ffn_w2 = (const float*)d_in[16];
    const float* ffn_b2 = (const float*)d_in[17];
    const float* bn_g   = (const float*)d_in[18];
    const float* bn_b   = (const float*)d_in[19];
    // d_in[20]=kernel(3), d_in[21]=pad(1) — compile-time constants here.

    float* buf = nullptr;
    cudaGetSymbolAddress((void**)&buf, g_scratch);
    float* Qb = buf + 0u * NEL;
    float* Kb = buf + 1u * NEL;
    float* Vb = buf + 2u * NEL;
    float* Ob = buf + 3u * NEL;
    float* T1 = buf + 4u * NEL;   // slf1
    float* T2 = buf + 5u * NEL;   // slf2
    float* C1 = buf + 6u * NEL;   // crs1
    float* C2 = buf + 7u * NEL;   // crs2
    float* Hh = buf + 8u * NEL;   // ffn hidden

    float* out1 = (float*)d_out;
    float* out2 = out1 + NEL;

    // slf1 = mha(input1, input1, slf...)
    run_mha(input1, input1, slf_wq, slf_wk, slf_wv, slf_fc, slf_g, slf_b,
            T1, Qb, Kb, Vb, Ob);
    // slf2 = mha(input2, input2, slf...)
    run_mha(input2, input2, slf_wq, slf_wk, slf_wv, slf_fc, slf_g, slf_b,
            T2, Qb, Kb, Vb, Ob);
    // crs1 = mha(slf1, slf2, crs...)
    run_mha(T1, T2, crs_wq, crs_wk, crs_wv, crs_fc, crs_g, crs_b,
            C1, Qb, Kb, Vb, Ob);
    // crs2 = mha(slf2, slf1, crs...)
    run_mha(T2, T1, crs_wq, crs_wk, crs_wv, crs_fc, crs_g, crs_b,
            C2, Qb, Kb, Vb, Ob);
    // out1 = ffn(crs1), out2 = ffn(crs2)
    run_ffn(C1, ffn_w1, ffn_b1, ffn_w2, ffn_b2, bn_g, bn_b, out1, Hh, Qb);
    run_ffn(C2, ffn_w1, ffn_b1, ffn_w2, ffn_b2, bn_g, bn_b, out2, Hh, Qb);
}

// round 3
// speedup vs baseline: 4.6900x; 4.6900x over previous
#include <cuda_runtime.h>
#include <cuda_bf16.h>
#include <cstdint>
#include <math.h>

// Problem constants
#define Bv   4
#define Cv   256
#define Hv   64
#define Wv   64
#define HW   4096          // Hv*Wv
#define NPIX 16384         // Bv*HW
#define NEL  4194304       // Bv*Cv*HW
#define NHEAD 8
#define DHEAD 32

// Scratch: 9 tensors of NEL floats (~151 MB), device global (no allocation).
__device__ float g_scratch[9u * NEL];

// ---------------------------------------------------------------------------
// PTX helpers
// ---------------------------------------------------------------------------
__device__ __forceinline__ void cp_async16(void* smem_dst, const void* gsrc) {
    uint32_t s = (uint32_t)__cvta_generic_to_shared(smem_dst);
    asm volatile("cp.async.ca.shared.global [%0], [%1], 16;\n" :: "r"(s), "l"(gsrc));
}
__device__ __forceinline__ void cp_commit() {
    asm volatile("cp.async.commit_group;\n");
}
__device__ __forceinline__ void cp_wait_all() {
    asm volatile("cp.async.wait_group 0;\n");
}
__device__ __forceinline__ uint32_t f2tf32(float x) {
    uint32_t y;
    asm("cvt.rna.tf32.f32 %0, %1;" : "=r"(y) : "f"(x));
    return y;
}
__device__ __forceinline__ void mma_tf32(float* d, const uint32_t* a, const uint32_t* b) {
    asm volatile(
        "mma.sync.aligned.m16n8k8.row.col.f32.tf32.tf32.f32 "
        "{%0,%1,%2,%3}, {%4,%5,%6,%7}, {%8,%9}, {%0,%1,%2,%3};\n"
        : "+f"(d[0]), "+f"(d[1]), "+f"(d[2]), "+f"(d[3])
        : "r"(a[0]), "r"(a[1]), "r"(a[2]), "r"(a[3]), "r"(b[0]), "r"(b[1]));
}

// ---------------------------------------------------------------------------
// conv1x1 as tf32 tensor-core GEMM: Y[m,n] = sum_k W[m,k] X[k,n] per batch.
// X element (b, c, p) at X[((b*Cv + c) << 12) + p].
// BM=128, BN=128, BK=32, 256 threads, warp tile 64x32 (m16n8k8 MMA).
// Smem: A[m][k] stride 36 (banks 4a+b -> conflict-free),
//       B[k][n] stride 136 (banks 8b+a -> conflict-free).
// 2-stage cp.async pipeline.
// ---------------------------------------------------------------------------
#define BK     32
#define A_STR  36
#define B_STR  136
#define A_SZ   (128 * A_STR)          // floats
#define B_SZ   (BK * B_STR)           // floats
#define STG    (A_SZ + B_SZ)          // floats per stage
#define SMEM_BYTES (2 * STG * 4)

template<bool RELU, bool BIAS, bool RES>
__global__ void conv1x1_tc_kernel(const float* __restrict__ X,
                                  const float* __restrict__ Wm,
                                  const float* __restrict__ bias,
                                  const float* __restrict__ res,
                                  float* __restrict__ Y)
{
    extern __shared__ float smem[];

    const int tb_n = blockIdx.x * 128;     // global column start
    const int tb_m = blockIdx.y * 128;     // output-channel start
    const int b    = tb_n >> 12;           // batch (128 divides HW)
    const int p0   = tb_n & 4095;          // pixel offset within batch

    const int t    = threadIdx.x;
    const int lane = t & 31;
    const int warp = t >> 5;
    const int wm0  = (warp >> 2) * 64;     // warp row offset within tile
    const int wn0  = (warp & 3) * 32;      // warp col offset within tile

    const float* Xbase = X + ((size_t)(b * Cv) << 12) + p0;

    float acc[4][4][4];
    #pragma unroll
    for (int i = 0; i < 4; i++)
        #pragma unroll
        for (int j = 0; j < 4; j++)
            #pragma unroll
            for (int r = 0; r < 4; r++) acc[i][j][r] = 0.0f;

    // tile loader: stage s, k-tile kt
    auto load_tile = [&](int kt, int s) {
        float* As = smem + s * STG;
        float* Bs = As + A_SZ;
        int k0 = kt * BK;
        #pragma unroll
        for (int i = 0; i < 4; i++) {
            int id = t + i * 256;          // 0..1023
            int m  = id >> 3;              // 0..127
            int kq = id & 7;               // float4 index in k
            cp_async16(&As[m * A_STR + kq * 4],
                       Wm + (size_t)(tb_m + m) * Cv + k0 + kq * 4);
        }
        #pragma unroll
        for (int i = 0; i < 4; i++) {
            int id = t + i * 256;
            int kk = id >> 5;              // 0..31
            int nq = id & 31;              // float4 index in n
            cp_async16(&Bs[kk * B_STR + nq * 4],
                       Xbase + ((size_t)(k0 + kk) << 12) + nq * 4);
        }
    };

    load_tile(0, 0);
    cp_commit();

    const int a_r = lane >> 2;
    const int a_c = lane & 3;

    int buf = 0;
    const int KT = Cv / BK;                // 8
    for (int kt = 0; kt < KT; kt++) {
        cp_wait_all();
        __syncthreads();
        if (kt + 1 < KT) { load_tile(kt + 1, buf ^ 1); cp_commit(); }

        const float* As = smem + buf * STG;
        const float* Bs = As + A_SZ;

        #pragma unroll
        for (int ks = 0; ks < 4; ks++) {
            int kb = ks * 8;
            uint32_t afr[4][4], bfr[4][2];
            #pragma unroll
            for (int mi = 0; mi < 4; mi++) {
                const float* ap = As + (wm0 + mi * 16 + a_r) * A_STR + kb + a_c;
                afr[mi][0] = f2tf32(ap[0]);
                afr[mi][1] = f2tf32(ap[8 * A_STR]);
                afr[mi][2] = f2tf32(ap[4]);
                afr[mi][3] = f2tf32(ap[8 * A_STR + 4]);
            }
            #pragma unroll
            for (int ni = 0; ni < 4; ni++) {
                const float* bp = Bs + (kb + a_c) * B_STR + wn0 + ni * 8 + a_r;
                bfr[ni][0] = f2tf32(bp[0]);
                bfr[ni][1] = f2tf32(bp[4 * B_STR]);
            }
            #pragma unroll
            for (int mi = 0; mi < 4; mi++)
                #pragma unroll
                for (int ni = 0; ni < 4; ni++)
                    mma_tf32(acc[mi][ni], afr[mi], bfr[ni]);
        }
        __syncthreads();
        buf ^= 1;
    }

    // Epilogue: each (mi,ni) fragment -> rows r, r+8; cols c, c+1 (float2)
    #pragma unroll
    for (int mi = 0; mi < 4; mi++) {
        int rbase = tb_m + wm0 + mi * 16 + a_r;
        float bv0 = BIAS ? bias[rbase]     : 0.0f;
        float bv1 = BIAS ? bias[rbase + 8] : 0.0f;
        #pragma unroll
        for (int ni = 0; ni < 4; ni++) {
            int cbase = p0 + wn0 + ni * 8 + 2 * a_c;
            size_t off0 = ((size_t)(b * Cv + rbase) << 12) + cbase;
            size_t off1 = off0 + ((size_t)8 << 12);

            float v0 = acc[mi][ni][0] + bv0;
            float v1 = acc[mi][ni][1] + bv0;
            float v2 = acc[mi][ni][2] + bv1;
            float v3 = acc[mi][ni][3] + bv1;
            if (RELU) {
                v0 = fmaxf(v0, 0.0f); v1 = fmaxf(v1, 0.0f);
                v2 = fmaxf(v2, 0.0f); v3 = fmaxf(v3, 0.0f);
            }
            if (RES) {
                float2 r0 = *(const float2*)(res + off0);
                float2 r1 = *(const float2*)(res + off1);
                v0 += r0.x; v1 += r0.y; v2 += r1.x; v3 += r1.y;
            }
            *(float2*)(Y + off0) = make_float2(v0, v1);
            *(float2*)(Y + off1) = make_float2(v2, v3);
        }
    }
}

// ---------------------------------------------------------------------------
// Local 3x3 windowed attention, one thread per (b, head, pixel).
// ---------------------------------------------------------------------------
__global__ void local_attn_kernel(const float* __restrict__ Q,
                                  const float* __restrict__ K,
                                  const float* __restrict__ V,
                                  float* __restrict__ O)
{
    int n = blockIdx.x * blockDim.x + threadIdx.x;   // 0 .. 131071
    int p    = n & 4095;
    int x    = p & 63;
    int y    = p >> 6;
    int head = (n >> 12) & 7;
    int b    = n >> 15;

    size_t chbase = ((size_t)(b * Cv + head * DHEAD)) << 12;

    float q[DHEAD];
    #pragma unroll
    for (int d = 0; d < DHEAD; d++) q[d] = Q[chbase + ((size_t)d << 12) + p];

    const float scale = 0.17677669529663687f; // 1/sqrt(32)

    float logits[9];
    #pragma unroll
    for (int ki = 0; ki < 3; ki++) {
        #pragma unroll
        for (int kj = 0; kj < 3; kj++) {
            int yy = y + ki - 1, xx = x + kj - 1;
            float acc = 0.0f;
            if (yy >= 0 && yy < Hv && xx >= 0 && xx < Wv) {
                int pp = yy * Wv + xx;
                #pragma unroll
                for (int d = 0; d < DHEAD; d++)
                    acc = fmaf(q[d], K[chbase + ((size_t)d << 12) + pp], acc);
                acc *= scale;
            }
            logits[ki * 3 + kj] = acc;
        }
    }

    float m = logits[0];
    #pragma unroll
    for (int i = 1; i < 9; i++) m = fmaxf(m, logits[i]);
    float wgt[9]; float s = 0.0f;
    #pragma unroll
    for (int i = 0; i < 9; i++) { wgt[i] = __expf(logits[i] - m); s += wgt[i]; }
    float inv = 1.0f / s;
    #pragma unroll
    for (int i = 0; i < 9; i++) wgt[i] *= inv;

    #pragma unroll
    for (int d = 0; d < DHEAD; d++) {
        float acc = 0.0f;
        #pragma unroll
        for (int ki = 0; ki < 3; ki++) {
            #pragma unroll
            for (int kj = 0; kj < 3; kj++) {
                int yy = y + ki - 1, xx = x + kj - 1;
                if (yy >= 0 && yy < Hv && xx >= 0 && xx < Wv)
                    acc = fmaf(wgt[ki * 3 + kj],
                               V[chbase + ((size_t)d << 12) + yy * Wv + xx], acc);
            }
        }
        O[chbase + ((size_t)d << 12) + p] = acc;
    }
}

// ---------------------------------------------------------------------------
// LayerNorm over channel dim, one thread per pixel (coalesced across pixels).
// ---------------------------------------------------------------------------
__global__ void layernorm_kernel(const float* __restrict__ X,
                                 const float* __restrict__ g,
                                 const float* __restrict__ bt,
                                 float* __restrict__ Y)
{
    int n = blockIdx.x * blockDim.x + threadIdx.x;   // 0 .. 16383
    int b = n >> 12, p = n & 4095;
    const float* xp = X + (((size_t)b * Cv) << 12) + p;
    float s = 0.0f, s2 = 0.0f;
    for (int c = 0; c < Cv; c++) {
        float v = xp[(size_t)c << 12];
        s += v; s2 += v * v;
    }
    float mu   = s * (1.0f / Cv);
    float var  = s2 * (1.0f / Cv) - mu * mu;
    float rstd = rsqrtf(var + 1e-6f);
    float* yp = Y + (((size_t)b * Cv) << 12) + p;
    for (int c = 0; c < Cv; c++) {
        float v = xp[(size_t)c << 12];
        yp[(size_t)c << 12] = (v - mu) * rstd * g[c] + bt[c];
    }
}

// ---------------------------------------------------------------------------
// BatchNorm over (B,H,W) per channel, fused +residual. One block per channel.
// ---------------------------------------------------------------------------
__global__ void batchnorm_kernel(const float* __restrict__ X,
                                 const float* __restrict__ g,
                                 const float* __restrict__ bt,
                                 const float* __restrict__ res,
                                 float* __restrict__ Y)
{
    int c = blockIdx.x;
    __shared__ float ssum[256], ssum2[256];
    float s = 0.0f, s2 = 0.0f;
    for (int b = 0; b < Bv; b++) {
        const float* xp = X + (((size_t)(b * Cv + c)) << 12);
        for (int p = threadIdx.x; p < HW; p += 256) {
            float v = xp[p];
            s += v; s2 += v * v;
        }
    }
    ssum[threadIdx.x] = s; ssum2[threadIdx.x] = s2;
    __syncthreads();
    for (int off = 128; off > 0; off >>= 1) {
        if (threadIdx.x < off) {
            ssum[threadIdx.x]  += ssum[threadIdx.x + off];
            ssum2[threadIdx.x] += ssum2[threadIdx.x + off];
        }
        __syncthreads();
    }
    float mu   = ssum[0] * (1.0f / (Bv * HW));
    float var  = ssum2[0] * (1.0f / (Bv * HW)) - mu * mu;
    float rstd = rsqrtf(var + 1e-5f);
    float gg = g[c], bb = bt[c];
    for (int b = 0; b < Bv; b++) {
        size_t off = ((size_t)(b * Cv + c)) << 12;
        for (int p = threadIdx.x; p < HW; p += 256)
            Y[off + p] = (X[off + p] - mu) * rstd * gg + bb + res[off + p];
    }
}

// ---------------------------------------------------------------------------
// Host-side orchestration
// ---------------------------------------------------------------------------
static void launch_conv(const float* X, const float* Wm, const float* bias,
                        const float* res, float* Y, int relu, int has_bias, int has_res)
{
    dim3 gg(NPIX / 128, Cv / 128), bb(256);
    if (!relu && !has_bias && !has_res)
        conv1x1_tc_kernel<false, false, false><<<gg, bb, SMEM_BYTES>>>(X, Wm, bias, res, Y);
    else if (!relu && !has_bias && has_res)
        conv1x1_tc_kernel<false, false, true><<<gg, bb, SMEM_BYTES>>>(X, Wm, bias, res, Y);
    else if (relu)
        conv1x1_tc_kernel<true, true, false><<<gg, bb, SMEM_BYTES>>>(X, Wm, bias, res, Y);
    else
        conv1x1_tc_kernel<false, true, false><<<gg, bb, SMEM_BYTES>>>(X, Wm, bias, res, Y);
}

static void run_mha(const float* xq, const float* xkv,
                    const float* wq, const float* wk, const float* wv,
                    const float* wfc, const float* g, const float* bt,
                    float* out, float* Qb, float* Kb, float* Vb, float* Ob)
{
    launch_conv(xq,  wq,  nullptr, nullptr, Qb, 0, 0, 0);
    launch_conv(xkv, wk,  nullptr, nullptr, Kb, 0, 0, 0);
    launch_conv(xkv, wv,  nullptr, nullptr, Vb, 0, 0, 0);
    local_attn_kernel<<<(Bv * NHEAD * HW) / 256, 256>>>(Qb, Kb, Vb, Ob);
    launch_conv(Ob, wfc, nullptr, xq, Qb, 0, 0, 1);
    layernorm_kernel<<<NPIX / 256, 256>>>(Qb, g, bt, out);
}

static void run_ffn(const float* x,
                    const float* w1, const float* b1,
                    const float* w2, const float* b2,
                    const float* g, const float* bt,
                    float* out, float* Hh, float* Tmp)
{
    launch_conv(x,  w1, b1, nullptr, Hh,  1, 1, 0);
    launch_conv(Hh, w2, b2, nullptr, Tmp, 0, 1, 0);
    batchnorm_kernel<<<Cv, 256>>>(Tmp, g, bt, x, out);
}

extern "C" void kernel_launch(void* const* d_in, const int* in_sizes, int n_in,
                              void* d_out, int out_size)
{
    const float* input1 = (const float*)d_in[0];
    const float* input2 = (const float*)d_in[1];
    const float* slf_wq = (const float*)d_in[2];
    const float* slf_wk = (const float*)d_in[3];
    const float* slf_wv = (const float*)d_in[4];
    const float* slf_fc = (const float*)d_in[5];
    const float* slf_g  = (const float*)d_in[6];
    const float* slf_b  = (const float*)d_in[7];
    const float* crs_wq = (const float*)d_in[8];
    const float* crs_wk = (const float*)d_in[9];
    const float* crs_wv = (const float*)d_in[10];
    const float* crs_fc = (const float*)d_in[11];
    const float* crs_g  = (const float*)d_in[12];
    const float* crs_b  = (const float*)d_in[13];
    const float* ffn_w1 = (const float*)d_in[14];
    const float* ffn_b1 = (const float*)d_in[15];
    const float* ffn_w2 = (const float*)d_in[16];
    const float* ffn_b2 = (const float*)d_in[17];
    const float* bn_g   = (const float*)d_in[18];
    const float* bn_b   = (const float*)d_in[19];

    // Allow 70KB dynamic smem on all conv template instantiations (host-side
    // setup; legal under graph capture, no allocations involved).
    cudaFuncSetAttribute(conv1x1_tc_kernel<false, false, false>,
                         cudaFuncAttributeMaxDynamicSharedMemorySize, SMEM_BYTES);
    cudaFuncSetAttribute(conv1x1_tc_kernel<false, false, true>,
                         cudaFuncAttributeMaxDynamicSharedMemorySize, SMEM_BYTES);
    cudaFuncSetAttribute(conv1x1_tc_kernel<true, true, false>,
                         cudaFuncAttributeMaxDynamicSharedMemorySize, SMEM_BYTES);
    cudaFuncSetAttribute(conv1x1_tc_kernel<false, true, false>,
                         cudaFuncAttributeMaxDynamicSharedMemorySize, SMEM_BYTES);

    float* buf = nullptr;
    cudaGetSymbolAddress((void**)&buf, g_scratch);
    float* Qb = buf + 0u * NEL;
    float* Kb = buf + 1u * NEL;
    float* Vb = buf + 2u * NEL;
    float* Ob = buf + 3u * NEL;
    float* T1 = buf + 4u * NEL;   // slf1
    float* T2 = buf + 5u * NEL;   // slf2
    float* C1 = buf + 6u * NEL;   // crs1
    float* C2 = buf + 7u * NEL;   // crs2
    float* Hh = buf + 8u * NEL;   // ffn hidden

    float* out1 = (float*)d_out;
    float* out2 = out1 + NEL;

    run_mha(input1, input1, slf_wq, slf_wk, slf_wv, slf_fc, slf_g, slf_b,
            T1, Qb, Kb, Vb, Ob);
    run_mha(input2, input2, slf_wq, slf_wk, slf_wv, slf_fc, slf_g, slf_b,
            T2, Qb, Kb, Vb, Ob);
    run_mha(T1, T2, crs_wq, crs_wk, crs_wv, crs_fc, crs_g, crs_b,
            C1, Qb, Kb, Vb, Ob);
    run_mha(T2, T1, crs_wq, crs_wk, crs_wv, crs_fc, crs_g, crs_b,
            C2, Qb, Kb, Vb, Ob);
    run_ffn(C1, ffn_w1, ffn_b1, ffn_w2, ffn_b2, bn_g, bn_b, out1, Hh, Qb);
    run_ffn(C2, ffn_w1, ffn_b1, ffn_w2, ffn_b2, bn_g, bn_b, out2, Hh, Qb);
}

// round 4
// speedup vs baseline: 5.3426x; 1.1392x over previous
#include <cuda_runtime.h>
#include <cuda_bf16.h>
#include <cstdint>
#include <math.h>

// Problem constants
#define Bv   4
#define Cv   256
#define Hv   64
#define Wv   64
#define HW   4096          // Hv*Wv
#define NPIX 16384         // Bv*HW
#define NEL  4194304       // Bv*Cv*HW
#define NHEAD 8
#define DHEAD 32
#define WELEM 65536        // 256*256 weight matrix elems
#define NWMAT 10

// Scratch: 9 tensors of NEL floats + 10 pre-rounded weight matrices.
__device__ float g_scratch[9u * NEL + NWMAT * WELEM];

// ---------------------------------------------------------------------------
// PTX helpers
// ---------------------------------------------------------------------------
__device__ __forceinline__ void cp_async16(void* smem_dst, const void* gsrc) {
    uint32_t s = (uint32_t)__cvta_generic_to_shared(smem_dst);
    asm volatile("cp.async.ca.shared.global [%0], [%1], 16;\n" :: "r"(s), "l"(gsrc));
}
__device__ __forceinline__ void cp_commit() {
    asm volatile("cp.async.commit_group;\n");
}
__device__ __forceinline__ void cp_wait_all() {
    asm volatile("cp.async.wait_group 0;\n");
}
__device__ __forceinline__ uint32_t f2tf32(float x) {
    uint32_t y;
    asm("cvt.rna.tf32.f32 %0, %1;" : "=r"(y) : "f"(x));
    return y;
}
__device__ __forceinline__ void mma_tf32(float* d, const uint32_t* a, const uint32_t* b) {
    asm volatile(
        "mma.sync.aligned.m16n8k8.row.col.f32.tf32.tf32.f32 "
        "{%0,%1,%2,%3}, {%4,%5,%6,%7}, {%8,%9}, {%0,%1,%2,%3};\n"
        : "+f"(d[0]), "+f"(d[1]), "+f"(d[2]), "+f"(d[3])
        : "r"(a[0]), "r"(a[1]), "r"(a[2]), "r"(a[3]), "r"(b[0]), "r"(b[1]));
}

// ---------------------------------------------------------------------------
// Pre-round 10 weight matrices to tf32 (RNA) once. Bit-identical to doing
// cvt.rna at mma time, but hoisted out of the GEMM inner loop.
// ---------------------------------------------------------------------------
struct WPtrs { const float* p[NWMAT]; };

__global__ void round_weights_kernel(WPtrs wp, float* __restrict__ dst) {
    int m = blockIdx.y;
    int i = blockIdx.x * blockDim.x + threadIdx.x;   // 0..65535
    dst[m * WELEM + i] = __uint_as_float(f2tf32(wp.p[m][i]));
}

// ---------------------------------------------------------------------------
// conv1x1 as tf32 tensor-core GEMM: Y[m,n] = sum_k W[m,k] X[k,n] per batch.
// W is PRE-ROUNDED to tf32 (no cvt on A path). X converted at use.
// BM=128, BN=128, BK=32, 256 threads, warp tile 64x32 (m16n8k8 MMA).
// ---------------------------------------------------------------------------
#define BK     32
#define A_STR  36
#define B_STR  136
#define A_SZ   (128 * A_STR)
#define B_SZ   (BK * B_STR)
#define STG    (A_SZ + B_SZ)
#define SMEM_BYTES (2 * STG * 4)

template<bool RELU, bool BIAS>
__global__ void conv1x1_tc_kernel(const float* __restrict__ X,
                                  const float* __restrict__ Wm,
                                  const float* __restrict__ bias,
                                  float* __restrict__ Y)
{
    extern __shared__ float smem[];

    const int tb_n = blockIdx.x * 128;
    const int tb_m = blockIdx.y * 128;
    const int b    = tb_n >> 12;
    const int p0   = tb_n & 4095;

    const int t    = threadIdx.x;
    const int lane = t & 31;
    const int warp = t >> 5;
    const int wm0  = (warp >> 2) * 64;
    const int wn0  = (warp & 3) * 32;

    const float* Xbase = X + ((size_t)(b * Cv) << 12) + p0;

    float acc[4][4][4];
    #pragma unroll
    for (int i = 0; i < 4; i++)
        #pragma unroll
        for (int j = 0; j < 4; j++)
            #pragma unroll
            for (int r = 0; r < 4; r++) acc[i][j][r] = 0.0f;

    auto load_tile = [&](int kt, int s) {
        float* As = smem + s * STG;
        float* Bs = As + A_SZ;
        int k0 = kt * BK;
        #pragma unroll
        for (int i = 0; i < 4; i++) {
            int id = t + i * 256;
            int m  = id >> 3;
            int kq = id & 7;
            cp_async16(&As[m * A_STR + kq * 4],
                       Wm + (size_t)(tb_m + m) * Cv + k0 + kq * 4);
        }
        #pragma unroll
        for (int i = 0; i < 4; i++) {
            int id = t + i * 256;
            int kk = id >> 5;
            int nq = id & 31;
            cp_async16(&Bs[kk * B_STR + nq * 4],
                       Xbase + ((size_t)(k0 + kk) << 12) + nq * 4);
        }
    };

    load_tile(0, 0);
    cp_commit();

    const int a_r = lane >> 2;
    const int a_c = lane & 3;

    int buf = 0;
    const int KT = Cv / BK;
    for (int kt = 0; kt < KT; kt++) {
        cp_wait_all();
        __syncthreads();
        if (kt + 1 < KT) { load_tile(kt + 1, buf ^ 1); cp_commit(); }

        const float* As = smem + buf * STG;
        const float* Bs = As + A_SZ;

        #pragma unroll
        for (int ks = 0; ks < 4; ks++) {
            int kb = ks * 8;
            uint32_t afr[4][4], bfr[4][2];
            #pragma unroll
            for (int mi = 0; mi < 4; mi++) {
                const float* ap = As + (wm0 + mi * 16 + a_r) * A_STR + kb + a_c;
                afr[mi][0] = __float_as_uint(ap[0]);
                afr[mi][1] = __float_as_uint(ap[8 * A_STR]);
                afr[mi][2] = __float_as_uint(ap[4]);
                afr[mi][3] = __float_as_uint(ap[8 * A_STR + 4]);
            }
            #pragma unroll
            for (int ni = 0; ni < 4; ni++) {
                const float* bp = Bs + (kb + a_c) * B_STR + wn0 + ni * 8 + a_r;
                bfr[ni][0] = f2tf32(bp[0]);
                bfr[ni][1] = f2tf32(bp[4 * B_STR]);
            }
            #pragma unroll
            for (int mi = 0; mi < 4; mi++)
                #pragma unroll
                for (int ni = 0; ni < 4; ni++)
                    mma_tf32(acc[mi][ni], afr[mi], bfr[ni]);
        }
        __syncthreads();
        buf ^= 1;
    }

    #pragma unroll
    for (int mi = 0; mi < 4; mi++) {
        int rbase = tb_m + wm0 + mi * 16 + a_r;
        float bv0 = BIAS ? bias[rbase]     : 0.0f;
        float bv1 = BIAS ? bias[rbase + 8] : 0.0f;
        #pragma unroll
        for (int ni = 0; ni < 4; ni++) {
            int cbase = p0 + wn0 + ni * 8 + 2 * a_c;
            size_t off0 = ((size_t)(b * Cv + rbase) << 12) + cbase;
            size_t off1 = off0 + ((size_t)8 << 12);

            float v0 = acc[mi][ni][0] + bv0;
            float v1 = acc[mi][ni][1] + bv0;
            float v2 = acc[mi][ni][2] + bv1;
            float v3 = acc[mi][ni][3] + bv1;
            if (RELU) {
                v0 = fmaxf(v0, 0.0f); v1 = fmaxf(v1, 0.0f);
                v2 = fmaxf(v2, 0.0f); v3 = fmaxf(v3, 0.0f);
            }
            *(float2*)(Y + off0) = make_float2(v0, v1);
            *(float2*)(Y + off1) = make_float2(v2, v3);
        }
    }
}

// ---------------------------------------------------------------------------
// Fused fc conv + residual + LayerNorm.
// BM=256 (all channels), BN=64, BK=32. 256 threads, 8 warps, warp tile 64x32.
// GEMM -> smem S[pixel][channel] (+residual) -> per-pixel LN -> gmem.
// ---------------------------------------------------------------------------
#define LA_STR 36
#define LB_STR 72
#define LA_SZ  (256 * LA_STR)
#define LB_SZ  (32 * LB_STR)
#define LSTG   (LA_SZ + LB_SZ)
#define LSMEM_BYTES (2 * LSTG * 4)   // 92160 B (>= 64*257*4 epilogue buffer)
#define S_STR  257

__global__ void convln_kernel(const float* __restrict__ X,
                              const float* __restrict__ Wm,
                              const float* __restrict__ res,
                              const float* __restrict__ g,
                              const float* __restrict__ bt,
                              float* __restrict__ Y)
{
    extern __shared__ float smem[];
    __shared__ float red[2][4][64];
    __shared__ float mus[64], rss[64];

    const int tb_n = blockIdx.x * 64;
    const int b    = tb_n >> 12;
    const int p0   = tb_n & 4095;

    const int t    = threadIdx.x;
    const int lane = t & 31;
    const int warp = t >> 5;
    const int wm0  = (warp >> 1) * 64;
    const int wn0  = (warp & 1) * 32;

    const float* Xbase = X + ((size_t)(b * Cv) << 12) + p0;

    float acc[4][4][4];
    #pragma unroll
    for (int i = 0; i < 4; i++)
        #pragma unroll
        for (int j = 0; j < 4; j++)
            #pragma unroll
            for (int r = 0; r < 4; r++) acc[i][j][r] = 0.0f;

    auto load_tile = [&](int kt, int s) {
        float* As = smem + s * LSTG;
        float* Bs = As + LA_SZ;
        int k0 = kt * BK;
        #pragma unroll
        for (int i = 0; i < 8; i++) {
            int id = t + i * 256;          // 0..2047
            int m  = id >> 3;              // 0..255
            int kq = id & 7;
            cp_async16(&As[m * LA_STR + kq * 4],
                       Wm + (size_t)m * Cv + k0 + kq * 4);
        }
        #pragma unroll
        for (int i = 0; i < 2; i++) {
            int id = t + i * 256;          // 0..511
            int kk = id >> 4;              // 0..31
            int nq = id & 15;              // 0..15
            cp_async16(&Bs[kk * LB_STR + nq * 4],
                       Xbase + ((size_t)(k0 + kk) << 12) + nq * 4);
        }
    };

    load_tile(0, 0);
    cp_commit();

    const int a_r = lane >> 2;
    const int a_c = lane & 3;

    int buf = 0;
    const int KT = Cv / BK;
    for (int kt = 0; kt < KT; kt++) {
        cp_wait_all();
        __syncthreads();
        if (kt + 1 < KT) { load_tile(kt + 1, buf ^ 1); cp_commit(); }

        const float* As = smem + buf * LSTG;
        const float* Bs = As + LA_SZ;

        #pragma unroll
        for (int ks = 0; ks < 4; ks++) {
            int kb = ks * 8;
            uint32_t afr[4][4], bfr[4][2];
            #pragma unroll
            for (int mi = 0; mi < 4; mi++) {
                const float* ap = As + (wm0 + mi * 16 + a_r) * LA_STR + kb + a_c;
                afr[mi][0] = __float_as_uint(ap[0]);
                afr[mi][1] = __float_as_uint(ap[8 * LA_STR]);
                afr[mi][2] = __float_as_uint(ap[4]);
                afr[mi][3] = __float_as_uint(ap[8 * LA_STR + 4]);
            }
            #pragma unroll
            for (int ni = 0; ni < 4; ni++) {
                const float* bp = Bs + (kb + a_c) * LB_STR + wn0 + ni * 8 + a_r;
                bfr[ni][0] = f2tf32(bp[0]);
                bfr[ni][1] = f2tf32(bp[4 * LB_STR]);
            }
            #pragma unroll
            for (int mi = 0; mi < 4; mi++)
                #pragma unroll
                for (int ni = 0; ni < 4; ni++)
                    mma_tf32(acc[mi][ni], afr[mi], bfr[ni]);
        }
        __syncthreads();
        buf ^= 1;
    }

    // Epilogue phase 1: fragments + residual -> S[pixel][channel]
    float* S = smem;                       // [64][S_STR], overlays pipeline bufs
    #pragma unroll
    for (int mi = 0; mi < 4; mi++) {
        int rbase = wm0 + mi * 16 + a_r;   // channel
        #pragma unroll
        for (int ni = 0; ni < 4; ni++) {
            int cbase = wn0 + ni * 8 + 2 * a_c;   // pixel within 64
            size_t off0 = ((size_t)(b * Cv + rbase) << 12) + p0 + cbase;
            size_t off1 = off0 + ((size_t)8 << 12);
            float2 r0 = *(const float2*)(res + off0);
            float2 r1 = *(const float2*)(res + off1);
            S[cbase * S_STR + rbase]           = acc[mi][ni][0] + r0.x;
            S[(cbase + 1) * S_STR + rbase]     = acc[mi][ni][1] + r0.y;
            S[cbase * S_STR + rbase + 8]       = acc[mi][ni][2] + r1.x;
            S[(cbase + 1) * S_STR + rbase + 8] = acc[mi][ni][3] + r1.y;
        }
    }
    __syncthreads();

    // Phase 2: per-pixel mean/var. thread t: pixel p=t&63, quarter q=t>>6.
    {
        int p = t & 63, q = t >> 6;
        float s = 0.0f, s2 = 0.0f;
        const float* row = S + p * S_STR + q * 64;
        #pragma unroll 8
        for (int j = 0; j < 64; j++) { float v = row[j]; s += v; s2 += v * v; }
        red[0][q][p] = s; red[1][q][p] = s2;
    }
    __syncthreads();
    if (t < 64) {
        float s  = red[0][0][t] + red[0][1][t] + red[0][2][t] + red[0][3][t];
        float s2 = red[1][0][t] + red[1][1][t] + red[1][2][t] + red[1][3][t];
        float mu  = s * (1.0f / Cv);
        float var = s2 * (1.0f / Cv) - mu * mu;
        mus[t] = mu;
        rss[t] = rsqrtf(var + 1e-6f);
    }
    __syncthreads();

    // Phase 3: normalize + write. thread t: pixel p=t&63, channels (t>>6)+4i.
    {
        int p = t & 63;
        float mu = mus[p], rstd = rss[p];
        int c0 = t >> 6;
        #pragma unroll 4
        for (int i = 0; i < 64; i++) {
            int c = c0 + 4 * i;
            float v = S[p * S_STR + c];
            Y[((size_t)(b * Cv + c) << 12) + p0 + p] =
                (v - mu) * rstd * g[c] + bt[c];
        }
    }
}

// ---------------------------------------------------------------------------
// Local 3x3 windowed attention, split over d: 2 threads per (b, head, pixel),
// each handling 16 of 32 channels. Halves live in different warps (t>>7) so
// per-warp loads stay coalesced; partial logits exchanged via smem.
// ---------------------------------------------------------------------------
__global__ void local_attn2_kernel(const float* __restrict__ Q,
                                   const float* __restrict__ K,
                                   const float* __restrict__ V,
                                   float* __restrict__ O)
{
    __shared__ float lg[256][11];

    const int t = threadIdx.x;
    const int u = blockIdx.x * 128 + (t & 127);   // pixel-head unit
    const int h = t >> 7;                         // d-half

    int p    = u & 4095;
    int x    = p & 63;
    int y    = p >> 6;
    int head = (u >> 12) & 7;
    int b    = u >> 15;

    size_t chbase = ((size_t)(b * Cv + head * DHEAD + h * 16)) << 12;

    float q[16];
    #pragma unroll
    for (int d = 0; d < 16; d++) q[d] = Q[chbase + ((size_t)d << 12) + p];

    float lgt[9];
    #pragma unroll
    for (int ki = 0; ki < 3; ki++) {
        #pragma unroll
        for (int kj = 0; kj < 3; kj++) {
            int yy = y + ki - 1, xx = x + kj - 1;
            float acc = 0.0f;
            if (yy >= 0 && yy < Hv && xx >= 0 && xx < Wv) {
                int pp = yy * Wv + xx;
                #pragma unroll
                for (int d = 0; d < 16; d++)
                    acc = fmaf(q[d], K[chbase + ((size_t)d << 12) + pp], acc);
            }
            lgt[ki * 3 + kj] = acc;
        }
    }

    #pragma unroll
    for (int j = 0; j < 9; j++) lg[t][j] = lgt[j];
    __syncthreads();

    const float scale = 0.17677669529663687f; // 1/sqrt(32)
    const int pt = t ^ 128;
    #pragma unroll
    for (int j = 0; j < 9; j++) lgt[j] = (lgt[j] + lg[pt][j]) * scale;

    float m = lgt[0];
    #pragma unroll
    for (int i = 1; i < 9; i++) m = fmaxf(m, lgt[i]);
    float wgt[9]; float s = 0.0f;
    #pragma unroll
    for (int i = 0; i < 9; i++) { wgt[i] = __expf(lgt[i] - m); s += wgt[i]; }
    float inv = 1.0f / s;
    #pragma unroll
    for (int i = 0; i < 9; i++) wgt[i] *= inv;

    #pragma unroll
    for (int d = 0; d < 16; d++) {
        float acc = 0.0f;
        #pragma unroll
        for (int ki = 0; ki < 3; ki++) {
            #pragma unroll
            for (int kj = 0; kj < 3; kj++) {
                int yy = y + ki - 1, xx = x + kj - 1;
                if (yy >= 0 && yy < Hv && xx >= 0 && xx < Wv)
                    acc = fmaf(wgt[ki * 3 + kj],
                               V[chbase + ((size_t)d << 12) + yy * Wv + xx], acc);
            }
        }
        O[chbase + ((size_t)d << 12) + p] = acc;
    }
}

// ---------------------------------------------------------------------------
// BatchNorm over (B,H,W) per channel, fused +residual. One block per channel.
// ---------------------------------------------------------------------------
__global__ void batchnorm_kernel(const float* __restrict__ X,
                                 const float* __restrict__ g,
                                 const float* __restrict__ bt,
                                 const float* __restrict__ res,
                                 float* __restrict__ Y)
{
    int c = blockIdx.x;
    __shared__ float ssum[256], ssum2[256];
    float s = 0.0f, s2 = 0.0f;
    for (int b = 0; b < Bv; b++) {
        const float* xp = X + (((size_t)(b * Cv + c)) << 12);
        for (int p = threadIdx.x; p < HW; p += 256) {
            float v = xp[p];
            s += v; s2 += v * v;
        }
    }
    ssum[threadIdx.x] = s; ssum2[threadIdx.x] = s2;
    __syncthreads();
    for (int off = 128; off > 0; off >>= 1) {
        if (threadIdx.x < off) {
            ssum[threadIdx.x]  += ssum[threadIdx.x + off];
            ssum2[threadIdx.x] += ssum2[threadIdx.x + off];
        }
        __syncthreads();
    }
    float mu   = ssum[0] * (1.0f / (Bv * HW));
    float var  = ssum2[0] * (1.0f / (Bv * HW)) - mu * mu;
    float rstd = rsqrtf(var + 1e-5f);
    float gg = g[c], bb = bt[c];
    for (int b = 0; b < Bv; b++) {
        size_t off = ((size_t)(b * Cv + c)) << 12;
        for (int p = threadIdx.x; p < 256 * 16; p += 256) {}
        for (int p = threadIdx.x; p < HW; p += 256)
            Y[off + p] = (X[off + p] - mu) * rstd * gg + bb + res[off + p];
    }
}

// ---------------------------------------------------------------------------
// Host-side orchestration
// ---------------------------------------------------------------------------
static void launch_conv(const float* X, const float* Wm, const float* bias,
                        float* Y, int relu, int has_bias)
{
    dim3 gg(NPIX / 128, Cv / 128), bb(256);
    if (relu)
        conv1x1_tc_kernel<true, true><<<gg, bb, SMEM_BYTES>>>(X, Wm, bias, Y);
    else if (has_bias)
        conv1x1_tc_kernel<false, true><<<gg, bb, SMEM_BYTES>>>(X, Wm, bias, Y);
    else
        conv1x1_tc_kernel<false, false><<<gg, bb, SMEM_BYTES>>>(X, Wm, bias, Y);
}

static void run_mha(const float* xq, const float* xkv,
                    const float* wq, const float* wk, const float* wv,
                    const float* wfc, const float* g, const float* bt,
                    float* out, float* Qb, float* Kb, float* Vb, float* Ob)
{
    launch_conv(xq,  wq, nullptr, Qb, 0, 0);
    launch_conv(xkv, wk, nullptr, Kb, 0, 0);
    launch_conv(xkv, wv, nullptr, Vb, 0, 0);
    local_attn2_kernel<<<(Bv * NHEAD * HW * 2) / 256, 256>>>(Qb, Kb, Vb, Ob);
    convln_kernel<<<NPIX / 64, 256, LSMEM_BYTES>>>(Ob, wfc, xq, g, bt, out);
}

static void run_ffn(const float* x,
                    const float* w1, const float* b1,
                    const float* w2, const float* b2,
                    const float* g, const float* bt,
                    float* out, float* Hh, float* Tmp)
{
    launch_conv(x,  w1, b1, Hh,  1, 1);
    launch_conv(Hh, w2, b2, Tmp, 0, 1);
    batchnorm_kernel<<<Cv, 256>>>(Tmp, g, bt, x, out);
}

extern "C" void kernel_launch(void* const* d_in, const int* in_sizes, int n_in,
                              void* d_out, int out_size)
{
    const float* input1 = (const float*)d_in[0];
    const float* input2 = (const float*)d_in[1];
    const float* slf_wq = (const float*)d_in[2];
    const float* slf_wk = (const float*)d_in[3];
    const float* slf_wv = (const float*)d_in[4];
    const float* slf_fc = (const float*)d_in[5];
    const float* slf_g  = (const float*)d_in[6];
    const float* slf_b  = (const float*)d_in[7];
    const float* crs_wq = (const float*)d_in[8];
    const float* crs_wk = (const float*)d_in[9];
    const float* crs_wv = (const float*)d_in[10];
    const float* crs_fc = (const float*)d_in[11];
    const float* crs_g  = (const float*)d_in[12];
    const float* crs_b  = (const float*)d_in[13];
    const float* ffn_w1 = (const float*)d_in[14];
    const float* ffn_b1 = (const float*)d_in[15];
    const float* ffn_w2 = (const float*)d_in[16];
    const float* ffn_b2 = (const float*)d_in[17];
    const float* bn_g   = (const float*)d_in[18];
    const float* bn_b   = (const float*)d_in[19];

    cudaFuncSetAttribute(conv1x1_tc_kernel<false, false>,
                         cudaFuncAttributeMaxDynamicSharedMemorySize, SMEM_BYTES);
    cudaFuncSetAttribute(conv1x1_tc_kernel<true, true>,
                         cudaFuncAttributeMaxDynamicSharedMemorySize, SMEM_BYTES);
    cudaFuncSetAttribute(conv1x1_tc_kernel<false, true>,
                         cudaFuncAttributeMaxDynamicSharedMemorySize, SMEM_BYTES);
    cudaFuncSetAttribute(convln_kernel,
                         cudaFuncAttributeMaxDynamicSharedMemorySize, LSMEM_BYTES);

    float* buf = nullptr;
    cudaGetSymbolAddress((void**)&buf, g_scratch);
    float* Qb = buf + 0u * NEL;
    float* Kb = buf + 1u * NEL;
    float* Vb = buf + 2u * NEL;
    float* Ob = buf + 3u * NEL;
    float* T1 = buf + 4u * NEL;   // slf1
    float* T2 = buf + 5u * NEL;   // slf2
    float* C1 = buf + 6u * NEL;   // crs1
    float* C2 = buf + 7u * NEL;   // crs2
    float* Hh = buf + 8u * NEL;   // ffn hidden
    float* W8 = buf + 9u * NEL;   // pre-rounded weights

    // Pre-round all weight matrices to tf32 (RNA) once.
    WPtrs wp;
    wp.p[0] = slf_wq; wp.p[1] = slf_wk; wp.p[2] = slf_wv; wp.p[3] = slf_fc;
    wp.p[4] = crs_wq; wp.p[5] = crs_wk; wp.p[6] = crs_wv; wp.p[7] = crs_fc;
    wp.p[8] = ffn_w1; wp.p[9] = ffn_w2;
    round_weights_kernel<<<dim3(WELEM / 1024, NWMAT), 1024>>>(wp, W8);

    const float* rwq  = W8 + 0 * WELEM;
    const float* rwk  = W8 + 1 * WELEM;
    const float* rwv  = W8 + 2 * WELEM;
    const float* rwfc = W8 + 3 * WELEM;
    const float* cwq  = W8 + 4 * WELEM;
    const float* cwk  = W8 + 5 * WELEM;
    const float* cwv  = W8 + 6 * WELEM;
    const float* cwfc = W8 + 7 * WELEM;
    const float* rw1  = W8 + 8 * WELEM;
    const float* rw2  = W8 + 9 * WELEM;

    float* out1 = (float*)d_out;
    float* out2 = out1 + NEL;

    run_mha(input1, input1, rwq, rwk, rwv, rwfc, slf_g, slf_b,
            T1, Qb, Kb, Vb, Ob);
    run_mha(input2, input2, rwq, rwk, rwv, rwfc, slf_g, slf_b,
            T2, Qb, Kb, Vb, Ob);
    run_mha(T1, T2, cwq, cwk, cwv, cwfc, crs_g, crs_b,
            C1, Qb, Kb, Vb, Ob);
    run_mha(T2, T1, cwq, cwk, cwv, cwfc, crs_g, crs_b,
            C2, Qb, Kb, Vb, Ob);
    run_ffn(C1, rw1, ffn_b1, rw2, ffn_b2, bn_g, bn_b, out1, Hh, Qb);
    run_ffn(C2, rw1, ffn_b1, rw2, ffn_b2, bn_g, bn_b, out2, Hh, Kb);
}